// round 12
// baseline (speedup 1.0000x reference)
#include <cuda_runtime.h>
#include <math.h>

#define BN_EPS 1e-5f
#define NN_EPS 1e-8f

// Transposed feature scratch: [B=8][N2=4096][C=128]
__device__ float g_ft[8 * 4096 * 128];
// kNN result scratch: per query 8 floats: w0,w1,w2, idx0,idx1,idx2 (bitcast), pad2
__device__ float g_nn[8 * 16384 * 8];
// z-sorted candidate scratch (SoA) + permutation
__device__ float g_sx[8 * 4096];
__device__ float g_sy[8 * 4096];
__device__ float g_sz[8 * 4096];
__device__ int   g_sid[8 * 4096];

// ---------------------------------------------------------------------------
// Kernel S: per-batch bitonic sort of p2 by z. 8 blocks x 1024 threads.
// Emits SoA (x, y, z) in z-ascending order + original-index permutation.
// ---------------------------------------------------------------------------
__global__ __launch_bounds__(1024) void sortz_kernel(const float* __restrict__ p2)
{
    __shared__ float key[4096];
    __shared__ int   val[4096];
    const int b = blockIdx.x;
    const int t = threadIdx.x;
    const float* pb = p2 + (size_t)b * 4096 * 3;

    for (int i = t; i < 4096; i += 1024) {
        key[i] = pb[i * 3 + 2];
        val[i] = i;
    }
    __syncthreads();

    for (int k = 2; k <= 4096; k <<= 1) {
        for (int j = k >> 1; j > 0; j >>= 1) {
            for (int i = t; i < 4096; i += 1024) {
                int ix = i ^ j;
                if (ix > i) {
                    bool up = ((i & k) == 0);
                    float ki = key[i], kx = key[ix];
                    if ((ki > kx) == up) {
                        key[i] = kx; key[ix] = ki;
                        int vi = val[i]; val[i] = val[ix]; val[ix] = vi;
                    }
                }
            }
            __syncthreads();
        }
    }

    for (int i = t; i < 4096; i += 1024) {
        int id = val[i];
        size_t o = (size_t)b * 4096 + i;
        g_sx[o]  = pb[id * 3 + 0];
        g_sy[o]  = pb[id * 3 + 1];
        g_sz[o]  = key[i];
        g_sid[o] = id;
    }
}

// ---------------------------------------------------------------------------
// Kernel A: fused (conv1x1 + BN + ReLU) x2, output transposed to [B, N2, C]
// (unchanged — ~93us)
// ---------------------------------------------------------------------------
__global__ __launch_bounds__(256) void fused_mlp_kernel(
    const float* __restrict__ f2,   // [8,256,4096]
    const float* __restrict__ W0,   // [128,256]
    const float* __restrict__ b0, const float* __restrict__ g0,
    const float* __restrict__ be0, const float* __restrict__ m0,
    const float* __restrict__ v0,
    const float* __restrict__ W1,   // [128,128]
    const float* __restrict__ b1, const float* __restrict__ g1,
    const float* __restrict__ be1, const float* __restrict__ m1,
    const float* __restrict__ v1)
{
    __shared__ float As[16][132];
    __shared__ float Bs[16][68];
    __shared__ float F1[128][68];

    const int b  = blockIdx.y;
    const int n0 = blockIdx.x * 64;
    const int t  = threadIdx.x;
    const int tx = t & 15;
    const int ty = t >> 4;

    float acc[8][4];
#pragma unroll
    for (int i = 0; i < 8; i++)
#pragma unroll
        for (int j = 0; j < 4; j++) acc[i][j] = 0.f;

    const float* f2b = f2 + ((size_t)b * 256) * 4096 + n0;

    for (int k0 = 0; k0 < 256; k0 += 16) {
#pragma unroll
        for (int i = 0; i < 2; i++) {
            int idx = t + i * 256;
            int m   = idx >> 2;
            int kk4 = (idx & 3) << 2;
            float4 v = *(const float4*)(W0 + m * 256 + k0 + kk4);
            As[kk4 + 0][m] = v.x; As[kk4 + 1][m] = v.y;
            As[kk4 + 2][m] = v.z; As[kk4 + 3][m] = v.w;
        }
        {
            int kk = t >> 4;
            int n4 = (t & 15) << 2;
            float4 v = *(const float4*)(f2b + (size_t)(k0 + kk) * 4096 + n4);
            *(float4*)&Bs[kk][n4] = v;
        }
        __syncthreads();
#pragma unroll
        for (int kk = 0; kk < 16; kk++) {
            float ra[8], rb[4];
            *(float4*)&ra[0] = *(const float4*)&As[kk][ty * 8];
            *(float4*)&ra[4] = *(const float4*)&As[kk][ty * 8 + 4];
            *(float4*)&rb[0] = *(const float4*)&Bs[kk][tx * 4];
#pragma unroll
            for (int i = 0; i < 8; i++)
#pragma unroll
                for (int j = 0; j < 4; j++)
                    acc[i][j] = fmaf(ra[i], rb[j], acc[i][j]);
        }
        __syncthreads();
    }

#pragma unroll
    for (int i = 0; i < 8; i++) {
        int m = ty * 8 + i;
        float sc = g0[m] * rsqrtf(v0[m] + BN_EPS);
        float bs = be0[m] + (b0[m] - m0[m]) * sc;
#pragma unroll
        for (int j = 0; j < 4; j++) {
            float y = fmaf(acc[i][j], sc, bs);
            F1[m][tx * 4 + j] = fmaxf(y, 0.f);
            acc[i][j] = 0.f;
        }
    }
    __syncthreads();

    for (int k0 = 0; k0 < 128; k0 += 16) {
#pragma unroll
        for (int i = 0; i < 2; i++) {
            int idx = t + i * 256;
            int m   = idx >> 2;
            int kk4 = (idx & 3) << 2;
            float4 v = *(const float4*)(W1 + m * 128 + k0 + kk4);
            As[kk4 + 0][m] = v.x; As[kk4 + 1][m] = v.y;
            As[kk4 + 2][m] = v.z; As[kk4 + 3][m] = v.w;
        }
        __syncthreads();
#pragma unroll
        for (int kk = 0; kk < 16; kk++) {
            float ra[8], rb[4];
            *(float4*)&ra[0] = *(const float4*)&As[kk][ty * 8];
            *(float4*)&ra[4] = *(const float4*)&As[kk][ty * 8 + 4];
            *(float4*)&rb[0] = *(const float4*)&F1[k0 + kk][tx * 4];
#pragma unroll
            for (int i = 0; i < 8; i++)
#pragma unroll
                for (int j = 0; j < 4; j++)
                    acc[i][j] = fmaf(ra[i], rb[j], acc[i][j]);
        }
        __syncthreads();
    }

    float sc1[8], bs1[8];
#pragma unroll
    for (int i = 0; i < 8; i++) {
        int m = ty * 8 + i;
        sc1[i] = g1[m] * rsqrtf(v1[m] + BN_EPS);
        bs1[i] = be1[m] + (b1[m] - m1[m]) * sc1[i];
    }
    float* ftb = g_ft + ((size_t)b * 4096 + n0) * 128;
#pragma unroll
    for (int j = 0; j < 4; j++) {
        int n = tx * 4 + j;
        float vals[8];
#pragma unroll
        for (int i = 0; i < 8; i++)
            vals[i] = fmaxf(fmaf(acc[i][j], sc1[i], bs1[i]), 0.f);
        float* dst = ftb + (size_t)n * 128 + ty * 8;
        *(float4*)dst       = *(float4*)&vals[0];
        *(float4*)(dst + 4) = *(float4*)&vals[4];
    }
}

// ---------------------------------------------------------------------------
// Kernel B1: exact 3-NN via sorted-z two-pointer sweep.
// SMEM: SoA (sx, sy, sz) of z-sorted candidates = exactly 48KB -> 4 blocks/SM.
// Per query: binary search z position, expand outward by |dz|, stop when
// dz^2 exceeds (3rd-best squared distance + slack). Partial metric
// d = |p|^2 - 2 q.p (same ordering as full scan; |q|^2 added at the end).
// ---------------------------------------------------------------------------
#define ZSENT 1e19f
__global__ __launch_bounds__(256) void knn_kernel(const float* __restrict__ p1)
{
    __shared__ float sx[4096];
    __shared__ float sy[4096];
    __shared__ float sz[4096];

    const int b = blockIdx.y;
    const int t = threadIdx.x;
    const int q = blockIdx.x * 256 + t;
    const size_t base = (size_t)b * 4096;

    for (int i = t; i < 4096; i += 256) {
        sx[i] = g_sx[base + i];
        sy[i] = g_sy[base + i];
        sz[i] = g_sz[base + i];
    }

    const float* p1q = p1 + ((size_t)b * 16384 + q) * 3;
    const float qx = p1q[0], qy = p1q[1], qz = p1q[2];
    const float s1 = fmaf(qx, qx, fmaf(qy, qy, qz * qz));
    const float ax = -2.f * qx, ay = -2.f * qy, az = -2.f * qz;

    __syncthreads();

    // binary search: first index with sz[i] >= qz
    int lo = 0, hi = 4096;
#pragma unroll 1
    while (lo < hi) {
        int mid = (lo + hi) >> 1;
        if (sz[mid] < qz) lo = mid + 1; else hi = mid;
    }

    int jl = lo - 1, jh = lo;
    float zl = 0.f, zh = 0.f, dzl = ZSENT, dzh = ZSENT;
    if (jl >= 0)   { zl = sz[jl]; dzl = qz - zl; }
    if (jh < 4096) { zh = sz[jh]; dzh = zh - qz; }

    float d0 = 3.4e38f, d1 = 3.4e38f, d2 = 3.4e38f;
    int   i0 = 0, i1 = 0, i2 = 0;

#pragma unroll 1
    while (true) {
        bool takeL = dzl < dzh;
        float dz = takeL ? dzl : dzh;
        if (dz * dz > d2 + s1 + 1e-5f) break;  // d2 huge early -> no break
        int   j = takeL ? jl : jh;
        float z = takeL ? zl : zh;
        float x = sx[j];
        float y = sy[j];
        float d = fmaf(x, x + ax, fmaf(y, y + ay, z * (z + az)));
        if (d < d2) {
            if (d < d1) {
                d2 = d1; i2 = i1;
                if (d < d0) { d1 = d0; i1 = i0; d0 = d; i0 = j; }
                else        { d1 = d;  i1 = j; }
            } else { d2 = d; i2 = j; }
        }
        if (takeL) {
            jl--;
            if (jl >= 0) { zl = sz[jl]; dzl = qz - zl; } else dzl = ZSENT;
        } else {
            jh++;
            if (jh < 4096) { zh = sz[jh]; dzh = zh - qz; } else dzh = ZSENT;
        }
    }

    // translate sorted positions -> original indices (3 L2 hits)
    int o0 = g_sid[base + i0];
    int o1 = g_sid[base + i1];
    int o2 = g_sid[base + i2];

    float D0 = d0 + s1, D1 = d1 + s1, D2 = d2 + s1;
    float r0 = 1.f / (D0 + NN_EPS);
    float r1 = 1.f / (D1 + NN_EPS);
    float r2 = 1.f / (D2 + NN_EPS);
    float inv = 1.f / (r0 + r1 + r2);
    float4* rec = (float4*)(g_nn + ((size_t)b * 16384 + q) * 8);
    rec[0] = make_float4(r0 * inv, r1 * inv, r2 * inv, __int_as_float(o0));
    rec[1] = make_float4(__int_as_float(o1), __int_as_float(o2), 0.f, 0.f);
}

// ---------------------------------------------------------------------------
// Kernel B2: weighted feature gather. 1 query/thread, coalesced output.
// ---------------------------------------------------------------------------
__global__ __launch_bounds__(256) void gather_kernel(
    float* __restrict__ out)        // [8,128,16384]
{
    const int b = blockIdx.y;
    const int q = blockIdx.x * 256 + threadIdx.x;

    const float4* rec = (const float4*)(g_nn + ((size_t)b * 16384 + q) * 8);
    float4 ra = rec[0];
    float4 rb = rec[1];
    float w0 = ra.x, w1 = ra.y, w2 = ra.z;
    int i0 = __float_as_int(ra.w);
    int i1 = __float_as_int(rb.x);
    int i2 = __float_as_int(rb.y);

    const float4* fA = (const float4*)(g_ft + ((size_t)b * 4096 + i0) * 128);
    const float4* fB = (const float4*)(g_ft + ((size_t)b * 4096 + i1) * 128);
    const float4* fC = (const float4*)(g_ft + ((size_t)b * 4096 + i2) * 128);
    float* ob = out + (size_t)b * 128 * 16384 + q;

#pragma unroll
    for (int cc = 0; cc < 4; cc++) {
        float a[32];
#pragma unroll
        for (int u = 0; u < 8; u++) {
            float4 vA = fA[cc * 8 + u];
            float4 vB = fB[cc * 8 + u];
            float4 vC = fC[cc * 8 + u];
            a[4 * u + 0] = fmaf(w0, vA.x, fmaf(w1, vB.x, w2 * vC.x));
            a[4 * u + 1] = fmaf(w0, vA.y, fmaf(w1, vB.y, w2 * vC.y));
            a[4 * u + 2] = fmaf(w0, vA.z, fmaf(w1, vB.z, w2 * vC.z));
            a[4 * u + 3] = fmaf(w0, vA.w, fmaf(w1, vB.w, w2 * vC.w));
        }
#pragma unroll
        for (int u = 0; u < 32; u++)
            ob[(size_t)(cc * 32 + u) * 16384] = a[u];
    }
}

// ---------------------------------------------------------------------------
extern "C" void kernel_launch(void* const* d_in, const int* in_sizes, int n_in,
                              void* d_out, int out_size) {
    const float* p1  = (const float*)d_in[0];
    const float* p2  = (const float*)d_in[1];
    const float* f2  = (const float*)d_in[2];
    const float* W0  = (const float*)d_in[3];
    const float* b0  = (const float*)d_in[4];
    const float* g0  = (const float*)d_in[5];
    const float* be0 = (const float*)d_in[6];
    const float* m0  = (const float*)d_in[7];
    const float* v0  = (const float*)d_in[8];
    const float* W1  = (const float*)d_in[9];
    const float* b1  = (const float*)d_in[10];
    const float* g1  = (const float*)d_in[11];
    const float* be1 = (const float*)d_in[12];
    const float* m1  = (const float*)d_in[13];
    const float* v1  = (const float*)d_in[14];
    float* out = (float*)d_out;

    sortz_kernel<<<8, 1024>>>(p2);

    dim3 gA(4096 / 64, 8);
    fused_mlp_kernel<<<gA, 256>>>(f2, W0, b0, g0, be0, m0, v0,
                                  W1, b1, g1, be1, m1, v1);

    dim3 gK(16384 / 256, 8);             // (64, 8) = 512 blocks
    knn_kernel<<<gK, 256>>>(p1);

    dim3 gG(16384 / 256, 8);
    gather_kernel<<<gG, 256>>>(out);
}

// round 14
// speedup vs baseline: 1.3045x; 1.3045x over previous
#include <cuda_runtime.h>
#include <math.h>

#define BN_EPS 1e-5f
#define NN_EPS 1e-8f

// Transposed feature scratch: [B=8][N2=4096][C=128]
__device__ float g_ft[8 * 4096 * 128];
// kNN result scratch: per query 8 floats: w0,w1,w2, idx0,idx1,idx2 (bitcast), pad2
__device__ float g_nn[8 * 16384 * 8];

// ---------------------------------------------------------------------------
// Kernel A: fused (conv1x1 + BN + ReLU) x2, output transposed to [B, N2, C]
// (unchanged — ~93us)
// ---------------------------------------------------------------------------
__global__ __launch_bounds__(256) void fused_mlp_kernel(
    const float* __restrict__ f2,   // [8,256,4096]
    const float* __restrict__ W0,   // [128,256]
    const float* __restrict__ b0, const float* __restrict__ g0,
    const float* __restrict__ be0, const float* __restrict__ m0,
    const float* __restrict__ v0,
    const float* __restrict__ W1,   // [128,128]
    const float* __restrict__ b1, const float* __restrict__ g1,
    const float* __restrict__ be1, const float* __restrict__ m1,
    const float* __restrict__ v1)
{
    __shared__ float As[16][132];
    __shared__ float Bs[16][68];
    __shared__ float F1[128][68];

    const int b  = blockIdx.y;
    const int n0 = blockIdx.x * 64;
    const int t  = threadIdx.x;
    const int tx = t & 15;
    const int ty = t >> 4;

    float acc[8][4];
#pragma unroll
    for (int i = 0; i < 8; i++)
#pragma unroll
        for (int j = 0; j < 4; j++) acc[i][j] = 0.f;

    const float* f2b = f2 + ((size_t)b * 256) * 4096 + n0;

    for (int k0 = 0; k0 < 256; k0 += 16) {
#pragma unroll
        for (int i = 0; i < 2; i++) {
            int idx = t + i * 256;
            int m   = idx >> 2;
            int kk4 = (idx & 3) << 2;
            float4 v = *(const float4*)(W0 + m * 256 + k0 + kk4);
            As[kk4 + 0][m] = v.x; As[kk4 + 1][m] = v.y;
            As[kk4 + 2][m] = v.z; As[kk4 + 3][m] = v.w;
        }
        {
            int kk = t >> 4;
            int n4 = (t & 15) << 2;
            float4 v = *(const float4*)(f2b + (size_t)(k0 + kk) * 4096 + n4);
            *(float4*)&Bs[kk][n4] = v;
        }
        __syncthreads();
#pragma unroll
        for (int kk = 0; kk < 16; kk++) {
            float ra[8], rb[4];
            *(float4*)&ra[0] = *(const float4*)&As[kk][ty * 8];
            *(float4*)&ra[4] = *(const float4*)&As[kk][ty * 8 + 4];
            *(float4*)&rb[0] = *(const float4*)&Bs[kk][tx * 4];
#pragma unroll
            for (int i = 0; i < 8; i++)
#pragma unroll
                for (int j = 0; j < 4; j++)
                    acc[i][j] = fmaf(ra[i], rb[j], acc[i][j]);
        }
        __syncthreads();
    }

#pragma unroll
    for (int i = 0; i < 8; i++) {
        int m = ty * 8 + i;
        float sc = g0[m] * rsqrtf(v0[m] + BN_EPS);
        float bs = be0[m] + (b0[m] - m0[m]) * sc;
#pragma unroll
        for (int j = 0; j < 4; j++) {
            float y = fmaf(acc[i][j], sc, bs);
            F1[m][tx * 4 + j] = fmaxf(y, 0.f);
            acc[i][j] = 0.f;
        }
    }
    __syncthreads();

    for (int k0 = 0; k0 < 128; k0 += 16) {
#pragma unroll
        for (int i = 0; i < 2; i++) {
            int idx = t + i * 256;
            int m   = idx >> 2;
            int kk4 = (idx & 3) << 2;
            float4 v = *(const float4*)(W1 + m * 128 + k0 + kk4);
            As[kk4 + 0][m] = v.x; As[kk4 + 1][m] = v.y;
            As[kk4 + 2][m] = v.z; As[kk4 + 3][m] = v.w;
        }
        __syncthreads();
#pragma unroll
        for (int kk = 0; kk < 16; kk++) {
            float ra[8], rb[4];
            *(float4*)&ra[0] = *(const float4*)&As[kk][ty * 8];
            *(float4*)&ra[4] = *(const float4*)&As[kk][ty * 8 + 4];
            *(float4*)&rb[0] = *(const float4*)&F1[k0 + kk][tx * 4];
#pragma unroll
            for (int i = 0; i < 8; i++)
#pragma unroll
                for (int j = 0; j < 4; j++)
                    acc[i][j] = fmaf(ra[i], rb[j], acc[i][j]);
        }
        __syncthreads();
    }

    float sc1[8], bs1[8];
#pragma unroll
    for (int i = 0; i < 8; i++) {
        int m = ty * 8 + i;
        sc1[i] = g1[m] * rsqrtf(v1[m] + BN_EPS);
        bs1[i] = be1[m] + (b1[m] - m1[m]) * sc1[i];
    }
    float* ftb = g_ft + ((size_t)b * 4096 + n0) * 128;
#pragma unroll
    for (int j = 0; j < 4; j++) {
        int n = tx * 4 + j;
        float vals[8];
#pragma unroll
        for (int i = 0; i < 8; i++)
            vals[i] = fmaxf(fmaf(acc[i][j], sc1[i], bs1[i]), 0.f);
        float* dst = ftb + (size_t)n * 128 + ty * 8;
        *(float4*)dst       = *(float4*)&vals[0];
        *(float4*)(dst + 4) = *(float4*)&vals[4];
    }
}

// ---------------------------------------------------------------------------
// Kernel B1: brute-force 3-NN with min-of-4 batching.
// 1 query/thread, grid (64,8)=512 blocks x 256 thr. sp[j] is warp-uniform
// (broadcast LDS = 1 issue). Per 4 candidates: 4 LDS + 12 FMA + 3 min +
// 1 compare; the 4-way individual re-check runs only on a hit (~30x/query).
// Rank by partial = |p|^2 - 2 q.p ; |q|^2 added at the end.
// ---------------------------------------------------------------------------
__global__ __launch_bounds__(256) void knn_kernel(
    const float* __restrict__ p1,   // [8,16384,3]
    const float* __restrict__ p2)   // [8,4096,3]
{
    __shared__ float4 sp[2048];     // 32 KB

    const int b = blockIdx.y;
    const int t = threadIdx.x;
    const int q = blockIdx.x * 256 + t;

    const float* p1q = p1 + ((size_t)b * 16384 + q) * 3;
    const float qx = p1q[0], qy = p1q[1], qz = p1q[2];
    const float s1 = fmaf(qx, qx, fmaf(qy, qy, qz * qz));
    const float ax = -2.f * qx, ay = -2.f * qy, az = -2.f * qz;

    float d0 = 3.4e38f, d1 = 3.4e38f, d2 = 3.4e38f;
    int   i0 = 0, i1 = 0, i2 = 0;

#define KNN_INSERT(e, jj)                                              \
    if ((e) < d2) {                                                    \
        if ((e) < d1) {                                                \
            d2 = d1; i2 = i1;                                          \
            if ((e) < d0) { d1 = d0; i1 = i0; d0 = (e); i0 = (jj); }   \
            else          { d1 = (e); i1 = (jj); }                     \
        } else { d2 = (e); i2 = (jj); }                                \
    }

    const float* p2b = p2 + (size_t)b * 4096 * 3;
    for (int c0 = 0; c0 < 4096; c0 += 2048) {
        __syncthreads();
        for (int j = t; j < 2048; j += 256) {
            const float* pp = p2b + (size_t)(c0 + j) * 3;
            float x = pp[0], y = pp[1], z = pp[2];
            sp[j] = make_float4(x, y, z, fmaf(x, x, fmaf(y, y, z * z)));
        }
        __syncthreads();
#pragma unroll 2
        for (int j = 0; j < 2048; j += 4) {
            float4 P0 = sp[j + 0];
            float4 P1 = sp[j + 1];
            float4 P2 = sp[j + 2];
            float4 P3 = sp[j + 3];
            float e0 = fmaf(ax, P0.x, fmaf(ay, P0.y, fmaf(az, P0.z, P0.w)));
            float e1 = fmaf(ax, P1.x, fmaf(ay, P1.y, fmaf(az, P1.z, P1.w)));
            float e2 = fmaf(ax, P2.x, fmaf(ay, P2.y, fmaf(az, P2.z, P2.w)));
            float e3 = fmaf(ax, P3.x, fmaf(ay, P3.y, fmaf(az, P3.z, P3.w)));
            float m = fminf(fminf(e0, e1), fminf(e2, e3));
            if (m < d2) {                 // rare slow path
                int jj = c0 + j;
                KNN_INSERT(e0, jj + 0);
                KNN_INSERT(e1, jj + 1);
                KNN_INSERT(e2, jj + 2);
                KNN_INSERT(e3, jj + 3);
            }
        }
    }
#undef KNN_INSERT

    float D0 = d0 + s1, D1 = d1 + s1, D2 = d2 + s1;
    float r0 = 1.f / (D0 + NN_EPS);
    float r1 = 1.f / (D1 + NN_EPS);
    float r2 = 1.f / (D2 + NN_EPS);
    float inv = 1.f / (r0 + r1 + r2);
    float4* rec = (float4*)(g_nn + ((size_t)b * 16384 + q) * 8);
    rec[0] = make_float4(r0 * inv, r1 * inv, r2 * inv, __int_as_float(i0));
    rec[1] = make_float4(__int_as_float(i1), __int_as_float(i2), 0.f, 0.f);
}

// ---------------------------------------------------------------------------
// Kernel B2: weighted feature gather, 2 threads per query (64 channels each)
// -> 2x memory parallelism vs the 1-thread version (which was issue=4.3%,
// pure latency exposure). Grid (128,8) x 256 thr.
// Warp layout: t&127 = local query (consecutive -> coalesced), t>>7 = half.
// ---------------------------------------------------------------------------
__global__ __launch_bounds__(256) void gather_kernel(
    float* __restrict__ out)        // [8,128,16384]
{
    const int b = blockIdx.y;
    const int t = threadIdx.x;
    const int q    = blockIdx.x * 128 + (t & 127);
    const int half = t >> 7;              // 0: channels 0-63, 1: 64-127

    const float4* rec = (const float4*)(g_nn + ((size_t)b * 16384 + q) * 8);
    float4 ra = rec[0];
    float4 rb = rec[1];
    float w0 = ra.x, w1 = ra.y, w2 = ra.z;
    int i0 = __float_as_int(ra.w);
    int i1 = __float_as_int(rb.x);
    int i2 = __float_as_int(rb.y);

    const int coff = half * 64;           // channel offset
    const float4* fA = (const float4*)(g_ft + ((size_t)b * 4096 + i0) * 128 + coff);
    const float4* fB = (const float4*)(g_ft + ((size_t)b * 4096 + i1) * 128 + coff);
    const float4* fC = (const float4*)(g_ft + ((size_t)b * 4096 + i2) * 128 + coff);
    float* ob = out + ((size_t)b * 128 + coff) * 16384 + q;

#pragma unroll
    for (int cc = 0; cc < 2; cc++) {
        float a[32];
#pragma unroll
        for (int u = 0; u < 8; u++) {
            float4 vA = fA[cc * 8 + u];
            float4 vB = fB[cc * 8 + u];
            float4 vC = fC[cc * 8 + u];
            a[4 * u + 0] = fmaf(w0, vA.x, fmaf(w1, vB.x, w2 * vC.x));
            a[4 * u + 1] = fmaf(w0, vA.y, fmaf(w1, vB.y, w2 * vC.y));
            a[4 * u + 2] = fmaf(w0, vA.z, fmaf(w1, vB.z, w2 * vC.z));
            a[4 * u + 3] = fmaf(w0, vA.w, fmaf(w1, vB.w, w2 * vC.w));
        }
#pragma unroll
        for (int u = 0; u < 32; u++)
            ob[(size_t)(cc * 32 + u) * 16384] = a[u];
    }
}

// ---------------------------------------------------------------------------
extern "C" void kernel_launch(void* const* d_in, const int* in_sizes, int n_in,
                              void* d_out, int out_size) {
    const float* p1  = (const float*)d_in[0];
    const float* p2  = (const float*)d_in[1];
    const float* f2  = (const float*)d_in[2];
    const float* W0  = (const float*)d_in[3];
    const float* b0  = (const float*)d_in[4];
    const float* g0  = (const float*)d_in[5];
    const float* be0 = (const float*)d_in[6];
    const float* m0  = (const float*)d_in[7];
    const float* v0  = (const float*)d_in[8];
    const float* W1  = (const float*)d_in[9];
    const float* b1  = (const float*)d_in[10];
    const float* g1  = (const float*)d_in[11];
    const float* be1 = (const float*)d_in[12];
    const float* m1  = (const float*)d_in[13];
    const float* v1  = (const float*)d_in[14];
    float* out = (float*)d_out;

    dim3 gA(4096 / 64, 8);
    fused_mlp_kernel<<<gA, 256>>>(f2, W0, b0, g0, be0, m0, v0,
                                  W1, b1, g1, be1, m1, v1);

    dim3 gK(16384 / 256, 8);             // (64, 8) = 512 blocks
    knn_kernel<<<gK, 256>>>(p1, p2);

    dim3 gG(16384 / 128, 8);             // (128, 8) = 1024 blocks
    gather_kernel<<<gG, 256>>>(out);
}

// round 16
// speedup vs baseline: 2.0843x; 1.5978x over previous
#include <cuda_runtime.h>
#include <math.h>

#define BN_EPS 1e-5f
#define NN_EPS 1e-8f

// Transposed feature scratch: [B=8][N2=4096][C=128]
__device__ float g_ft[8 * 4096 * 128];

// ---------------------------------------------------------------------------
// Kernel A: fused (conv1x1 + BN + ReLU) x2, output transposed to [B, N2, C]
// (unchanged — ~93us at reference clock)
// ---------------------------------------------------------------------------
__global__ __launch_bounds__(256) void fused_mlp_kernel(
    const float* __restrict__ f2,   // [8,256,4096]
    const float* __restrict__ W0,   // [128,256]
    const float* __restrict__ b0, const float* __restrict__ g0,
    const float* __restrict__ be0, const float* __restrict__ m0,
    const float* __restrict__ v0,
    const float* __restrict__ W1,   // [128,128]
    const float* __restrict__ b1, const float* __restrict__ g1,
    const float* __restrict__ be1, const float* __restrict__ m1,
    const float* __restrict__ v1)
{
    __shared__ float As[16][132];
    __shared__ float Bs[16][68];
    __shared__ float F1[128][68];

    const int b  = blockIdx.y;
    const int n0 = blockIdx.x * 64;
    const int t  = threadIdx.x;
    const int tx = t & 15;
    const int ty = t >> 4;

    float acc[8][4];
#pragma unroll
    for (int i = 0; i < 8; i++)
#pragma unroll
        for (int j = 0; j < 4; j++) acc[i][j] = 0.f;

    const float* f2b = f2 + ((size_t)b * 256) * 4096 + n0;

    for (int k0 = 0; k0 < 256; k0 += 16) {
#pragma unroll
        for (int i = 0; i < 2; i++) {
            int idx = t + i * 256;
            int m   = idx >> 2;
            int kk4 = (idx & 3) << 2;
            float4 v = *(const float4*)(W0 + m * 256 + k0 + kk4);
            As[kk4 + 0][m] = v.x; As[kk4 + 1][m] = v.y;
            As[kk4 + 2][m] = v.z; As[kk4 + 3][m] = v.w;
        }
        {
            int kk = t >> 4;
            int n4 = (t & 15) << 2;
            float4 v = *(const float4*)(f2b + (size_t)(k0 + kk) * 4096 + n4);
            *(float4*)&Bs[kk][n4] = v;
        }
        __syncthreads();
#pragma unroll
        for (int kk = 0; kk < 16; kk++) {
            float ra[8], rb[4];
            *(float4*)&ra[0] = *(const float4*)&As[kk][ty * 8];
            *(float4*)&ra[4] = *(const float4*)&As[kk][ty * 8 + 4];
            *(float4*)&rb[0] = *(const float4*)&Bs[kk][tx * 4];
#pragma unroll
            for (int i = 0; i < 8; i++)
#pragma unroll
                for (int j = 0; j < 4; j++)
                    acc[i][j] = fmaf(ra[i], rb[j], acc[i][j]);
        }
        __syncthreads();
    }

#pragma unroll
    for (int i = 0; i < 8; i++) {
        int m = ty * 8 + i;
        float sc = g0[m] * rsqrtf(v0[m] + BN_EPS);
        float bs = be0[m] + (b0[m] - m0[m]) * sc;
#pragma unroll
        for (int j = 0; j < 4; j++) {
            float y = fmaf(acc[i][j], sc, bs);
            F1[m][tx * 4 + j] = fmaxf(y, 0.f);
            acc[i][j] = 0.f;
        }
    }
    __syncthreads();

    for (int k0 = 0; k0 < 128; k0 += 16) {
#pragma unroll
        for (int i = 0; i < 2; i++) {
            int idx = t + i * 256;
            int m   = idx >> 2;
            int kk4 = (idx & 3) << 2;
            float4 v = *(const float4*)(W1 + m * 128 + k0 + kk4);
            As[kk4 + 0][m] = v.x; As[kk4 + 1][m] = v.y;
            As[kk4 + 2][m] = v.z; As[kk4 + 3][m] = v.w;
        }
        __syncthreads();
#pragma unroll
        for (int kk = 0; kk < 16; kk++) {
            float ra[8], rb[4];
            *(float4*)&ra[0] = *(const float4*)&As[kk][ty * 8];
            *(float4*)&ra[4] = *(const float4*)&As[kk][ty * 8 + 4];
            *(float4*)&rb[0] = *(const float4*)&F1[k0 + kk][tx * 4];
#pragma unroll
            for (int i = 0; i < 8; i++)
#pragma unroll
                for (int j = 0; j < 4; j++)
                    acc[i][j] = fmaf(ra[i], rb[j], acc[i][j]);
        }
        __syncthreads();
    }

    float sc1[8], bs1[8];
#pragma unroll
    for (int i = 0; i < 8; i++) {
        int m = ty * 8 + i;
        sc1[i] = g1[m] * rsqrtf(v1[m] + BN_EPS);
        bs1[i] = be1[m] + (b1[m] - m1[m]) * sc1[i];
    }
    float* ftb = g_ft + ((size_t)b * 4096 + n0) * 128;
#pragma unroll
    for (int j = 0; j < 4; j++) {
        int n = tx * 4 + j;
        float vals[8];
#pragma unroll
        for (int i = 0; i < 8; i++)
            vals[i] = fmaxf(fmaf(acc[i][j], sc1[i], bs1[i]), 0.f);
        float* dst = ftb + (size_t)n * 128 + ty * 8;
        *(float4*)dst       = *(float4*)&vals[0];
        *(float4*)(dst + 4) = *(float4*)&vals[4];
    }
}

// ---------------------------------------------------------------------------
// Kernel B: FUSED 3-NN search + weighted gather (R4 structure, min-of-4 scan).
// 1 query/thread, grid (64,8)=512 blocks x 256 thr, p2 staged in SMEM as
// float4(x,y,z,|p|^2), 2 chunks of 2048. Fast path per 4 candidates:
// 4 broadcast LDS.128 + 12 FMA + 3 FMNMX + 1 cmp; insert tree only when
// min-of-4 beats current 3rd-best. No intermediate scratch traffic.
// Rank by partial = |p|^2 - 2 q.p ; |q|^2 added at the end.
// ---------------------------------------------------------------------------
__global__ __launch_bounds__(256) void interp_kernel(
    const float* __restrict__ p1,   // [8,16384,3]
    const float* __restrict__ p2,   // [8,4096,3]
    float* __restrict__ out)        // [8,128,16384]
{
    __shared__ float4 sp[2048];     // 32 KB

    const int b = blockIdx.y;
    const int t = threadIdx.x;
    const int q = blockIdx.x * 256 + t;

    const float* p1q = p1 + ((size_t)b * 16384 + q) * 3;
    const float qx = p1q[0], qy = p1q[1], qz = p1q[2];
    const float s1 = fmaf(qx, qx, fmaf(qy, qy, qz * qz));
    const float ax = -2.f * qx, ay = -2.f * qy, az = -2.f * qz;

    float d0 = 3.4e38f, d1 = 3.4e38f, d2 = 3.4e38f;
    int   i0 = 0, i1 = 0, i2 = 0;

#define KNN_INSERT(e, jj)                                              \
    if ((e) < d2) {                                                    \
        if ((e) < d1) {                                                \
            d2 = d1; i2 = i1;                                          \
            if ((e) < d0) { d1 = d0; i1 = i0; d0 = (e); i0 = (jj); }   \
            else          { d1 = (e); i1 = (jj); }                     \
        } else { d2 = (e); i2 = (jj); }                                \
    }

    const float* p2b = p2 + (size_t)b * 4096 * 3;
    for (int c0 = 0; c0 < 4096; c0 += 2048) {
        __syncthreads();
        for (int j = t; j < 2048; j += 256) {
            const float* pp = p2b + (size_t)(c0 + j) * 3;
            float x = pp[0], y = pp[1], z = pp[2];
            sp[j] = make_float4(x, y, z, fmaf(x, x, fmaf(y, y, z * z)));
        }
        __syncthreads();
#pragma unroll 2
        for (int j = 0; j < 2048; j += 4) {
            float4 P0 = sp[j + 0];
            float4 P1 = sp[j + 1];
            float4 P2 = sp[j + 2];
            float4 P3 = sp[j + 3];
            float e0 = fmaf(ax, P0.x, fmaf(ay, P0.y, fmaf(az, P0.z, P0.w)));
            float e1 = fmaf(ax, P1.x, fmaf(ay, P1.y, fmaf(az, P1.z, P1.w)));
            float e2 = fmaf(ax, P2.x, fmaf(ay, P2.y, fmaf(az, P2.z, P2.w)));
            float e3 = fmaf(ax, P3.x, fmaf(ay, P3.y, fmaf(az, P3.z, P3.w)));
            float m = fminf(fminf(e0, e1), fminf(e2, e3));
            if (m < d2) {                 // slow path: insert each candidate
                int jj = c0 + j;
                KNN_INSERT(e0, jj + 0);
                KNN_INSERT(e1, jj + 1);
                KNN_INSERT(e2, jj + 2);
                KNN_INSERT(e3, jj + 3);
            }
        }
    }
#undef KNN_INSERT

    // actual squared distances and normalized inverse-distance weights
    float D0 = d0 + s1, D1 = d1 + s1, D2 = d2 + s1;
    float r0 = 1.f / (D0 + NN_EPS);
    float r1 = 1.f / (D1 + NN_EPS);
    float r2 = 1.f / (D2 + NN_EPS);
    float inv = 1.f / (r0 + r1 + r2);
    float w0 = r0 * inv, w1 = r1 * inv, w2 = r2 * inv;

    const float4* fA = (const float4*)(g_ft + ((size_t)b * 4096 + i0) * 128);
    const float4* fB = (const float4*)(g_ft + ((size_t)b * 4096 + i1) * 128);
    const float4* fC = (const float4*)(g_ft + ((size_t)b * 4096 + i2) * 128);
    float* ob = out + (size_t)b * 128 * 16384 + q;

#pragma unroll
    for (int cc = 0; cc < 4; cc++) {
        float a[32];
#pragma unroll
        for (int u = 0; u < 8; u++) {
            float4 vA = fA[cc * 8 + u];
            float4 vB = fB[cc * 8 + u];
            float4 vC = fC[cc * 8 + u];
            a[4 * u + 0] = fmaf(w0, vA.x, fmaf(w1, vB.x, w2 * vC.x));
            a[4 * u + 1] = fmaf(w0, vA.y, fmaf(w1, vB.y, w2 * vC.y));
            a[4 * u + 2] = fmaf(w0, vA.z, fmaf(w1, vB.z, w2 * vC.z));
            a[4 * u + 3] = fmaf(w0, vA.w, fmaf(w1, vB.w, w2 * vC.w));
        }
#pragma unroll
        for (int u = 0; u < 32; u++)
            ob[(size_t)(cc * 32 + u) * 16384] = a[u];
    }
}

// ---------------------------------------------------------------------------
extern "C" void kernel_launch(void* const* d_in, const int* in_sizes, int n_in,
                              void* d_out, int out_size) {
    const float* p1  = (const float*)d_in[0];
    const float* p2  = (const float*)d_in[1];
    const float* f2  = (const float*)d_in[2];
    const float* W0  = (const float*)d_in[3];
    const float* b0  = (const float*)d_in[4];
    const float* g0  = (const float*)d_in[5];
    const float* be0 = (const float*)d_in[6];
    const float* m0  = (const float*)d_in[7];
    const float* v0  = (const float*)d_in[8];
    const float* W1  = (const float*)d_in[9];
    const float* b1  = (const float*)d_in[10];
    const float* g1  = (const float*)d_in[11];
    const float* be1 = (const float*)d_in[12];
    const float* m1  = (const float*)d_in[13];
    const float* v1  = (const float*)d_in[14];
    float* out = (float*)d_out;

    dim3 gA(4096 / 64, 8);
    fused_mlp_kernel<<<gA, 256>>>(f2, W0, b0, g0, be0, m0, v0,
                                  W1, b1, g1, be1, m1, v1);

    dim3 gB(16384 / 256, 8);             // (64, 8) = 512 blocks
    interp_kernel<<<gB, 256>>>(p1, p2, out);
}

// round 17
// speedup vs baseline: 2.1181x; 1.0162x over previous
#include <cuda_runtime.h>
#include <math.h>

#define BN_EPS 1e-5f
#define NN_EPS 1e-8f

// Transposed feature scratch: [B=8][N2=4096][C=128]
__device__ float g_ft[8 * 4096 * 128];

// ---- packed f32x2 helpers (sm_103a FFMA2 path; ptxas never emits these) ----
__device__ __forceinline__ unsigned long long pk2(float a, float b) {
    unsigned long long r;
    asm("mov.b64 %0, {%1, %2};" : "=l"(r) : "f"(a), "f"(b));
    return r;
}
__device__ __forceinline__ unsigned long long fma2(unsigned long long a,
                                                   unsigned long long b,
                                                   unsigned long long c) {
    unsigned long long d;
    asm("fma.rn.f32x2 %0, %1, %2, %3;" : "=l"(d) : "l"(a), "l"(b), "l"(c));
    return d;
}
__device__ __forceinline__ void upk2(unsigned long long v, float& lo, float& hi) {
    asm("mov.b64 {%0, %1}, %2;" : "=f"(lo), "=f"(hi) : "l"(v));
}

// ---------------------------------------------------------------------------
// Kernel A: fused (conv1x1 + BN + ReLU) x2, output transposed to [B, N2, C]
// (unchanged — ~93us at reference clock)
// ---------------------------------------------------------------------------
__global__ __launch_bounds__(256) void fused_mlp_kernel(
    const float* __restrict__ f2,   // [8,256,4096]
    const float* __restrict__ W0,   // [128,256]
    const float* __restrict__ b0, const float* __restrict__ g0,
    const float* __restrict__ be0, const float* __restrict__ m0,
    const float* __restrict__ v0,
    const float* __restrict__ W1,   // [128,128]
    const float* __restrict__ b1, const float* __restrict__ g1,
    const float* __restrict__ be1, const float* __restrict__ m1,
    const float* __restrict__ v1)
{
    __shared__ float As[16][132];
    __shared__ float Bs[16][68];
    __shared__ float F1[128][68];

    const int b  = blockIdx.y;
    const int n0 = blockIdx.x * 64;
    const int t  = threadIdx.x;
    const int tx = t & 15;
    const int ty = t >> 4;

    float acc[8][4];
#pragma unroll
    for (int i = 0; i < 8; i++)
#pragma unroll
        for (int j = 0; j < 4; j++) acc[i][j] = 0.f;

    const float* f2b = f2 + ((size_t)b * 256) * 4096 + n0;

    for (int k0 = 0; k0 < 256; k0 += 16) {
#pragma unroll
        for (int i = 0; i < 2; i++) {
            int idx = t + i * 256;
            int m   = idx >> 2;
            int kk4 = (idx & 3) << 2;
            float4 v = *(const float4*)(W0 + m * 256 + k0 + kk4);
            As[kk4 + 0][m] = v.x; As[kk4 + 1][m] = v.y;
            As[kk4 + 2][m] = v.z; As[kk4 + 3][m] = v.w;
        }
        {
            int kk = t >> 4;
            int n4 = (t & 15) << 2;
            float4 v = *(const float4*)(f2b + (size_t)(k0 + kk) * 4096 + n4);
            *(float4*)&Bs[kk][n4] = v;
        }
        __syncthreads();
#pragma unroll
        for (int kk = 0; kk < 16; kk++) {
            float ra[8], rb[4];
            *(float4*)&ra[0] = *(const float4*)&As[kk][ty * 8];
            *(float4*)&ra[4] = *(const float4*)&As[kk][ty * 8 + 4];
            *(float4*)&rb[0] = *(const float4*)&Bs[kk][tx * 4];
#pragma unroll
            for (int i = 0; i < 8; i++)
#pragma unroll
                for (int j = 0; j < 4; j++)
                    acc[i][j] = fmaf(ra[i], rb[j], acc[i][j]);
        }
        __syncthreads();
    }

#pragma unroll
    for (int i = 0; i < 8; i++) {
        int m = ty * 8 + i;
        float sc = g0[m] * rsqrtf(v0[m] + BN_EPS);
        float bs = be0[m] + (b0[m] - m0[m]) * sc;
#pragma unroll
        for (int j = 0; j < 4; j++) {
            float y = fmaf(acc[i][j], sc, bs);
            F1[m][tx * 4 + j] = fmaxf(y, 0.f);
            acc[i][j] = 0.f;
        }
    }
    __syncthreads();

    for (int k0 = 0; k0 < 128; k0 += 16) {
#pragma unroll
        for (int i = 0; i < 2; i++) {
            int idx = t + i * 256;
            int m   = idx >> 2;
            int kk4 = (idx & 3) << 2;
            float4 v = *(const float4*)(W1 + m * 128 + k0 + kk4);
            As[kk4 + 0][m] = v.x; As[kk4 + 1][m] = v.y;
            As[kk4 + 2][m] = v.z; As[kk4 + 3][m] = v.w;
        }
        __syncthreads();
#pragma unroll
        for (int kk = 0; kk < 16; kk++) {
            float ra[8], rb[4];
            *(float4*)&ra[0] = *(const float4*)&As[kk][ty * 8];
            *(float4*)&ra[4] = *(const float4*)&As[kk][ty * 8 + 4];
            *(float4*)&rb[0] = *(const float4*)&F1[k0 + kk][tx * 4];
#pragma unroll
            for (int i = 0; i < 8; i++)
#pragma unroll
                for (int j = 0; j < 4; j++)
                    acc[i][j] = fmaf(ra[i], rb[j], acc[i][j]);
        }
        __syncthreads();
    }

    float sc1[8], bs1[8];
#pragma unroll
    for (int i = 0; i < 8; i++) {
        int m = ty * 8 + i;
        sc1[i] = g1[m] * rsqrtf(v1[m] + BN_EPS);
        bs1[i] = be1[m] + (b1[m] - m1[m]) * sc1[i];
    }
    float* ftb = g_ft + ((size_t)b * 4096 + n0) * 128;
#pragma unroll
    for (int j = 0; j < 4; j++) {
        int n = tx * 4 + j;
        float vals[8];
#pragma unroll
        for (int i = 0; i < 8; i++)
            vals[i] = fmaxf(fmaf(acc[i][j], sc1[i], bs1[i]), 0.f);
        float* dst = ftb + (size_t)n * 128 + ty * 8;
        *(float4*)dst       = *(float4*)&vals[0];
        *(float4*)(dst + 4) = *(float4*)&vals[4];
    }
}

// ---------------------------------------------------------------------------
// Kernel B: FUSED 3-NN + weighted gather, f32x2-packed distance math.
// SMEM pair-interleaved: sxy[g]=(x2g,x2g+1,y2g,y2g+1), szw[g]=(z.., w..),
// where w=|p|^2. One ulonglong2 LDS.128 yields two packed operands (halves
// alias the register pair -> pack/unpack is free). Per 8 candidates:
// 8 LDS.128 + 12 FFMA2 + 7 FMNMX + 1 cmp fast path; insert tree on hit only.
// FMA association ax*x+(ay*y+(az*z+w)) identical to scalar version.
// ---------------------------------------------------------------------------
__global__ __launch_bounds__(256) void interp_kernel(
    const float* __restrict__ p1,   // [8,16384,3]
    const float* __restrict__ p2,   // [8,4096,3]
    float* __restrict__ out)        // [8,128,16384]
{
    __shared__ float4 sxy[1024];    // 16 KB (chunk of 2048 candidates)
    __shared__ float4 szw[1024];    // 16 KB

    const int b = blockIdx.y;
    const int t = threadIdx.x;
    const int q = blockIdx.x * 256 + t;

    const float* p1q = p1 + ((size_t)b * 16384 + q) * 3;
    const float qx = p1q[0], qy = p1q[1], qz = p1q[2];
    const float s1 = fmaf(qx, qx, fmaf(qy, qy, qz * qz));
    const float ax = -2.f * qx, ay = -2.f * qy, az = -2.f * qz;
    const unsigned long long ax2 = pk2(ax, ax);
    const unsigned long long ay2 = pk2(ay, ay);
    const unsigned long long az2 = pk2(az, az);

    float d0 = 3.4e38f, d1 = 3.4e38f, d2 = 3.4e38f;
    int   i0 = 0, i1 = 0, i2 = 0;

#define KNN_INSERT(e, jj)                                              \
    if ((e) < d2) {                                                    \
        if ((e) < d1) {                                                \
            d2 = d1; i2 = i1;                                          \
            if ((e) < d0) { d1 = d0; i1 = i0; d0 = (e); i0 = (jj); }   \
            else          { d1 = (e); i1 = (jj); }                     \
        } else { d2 = (e); i2 = (jj); }                                \
    }

    const float* p2b = p2 + (size_t)b * 4096 * 3;
    const ulonglong2* sxyp = (const ulonglong2*)sxy;  // .x=x-pair, .y=y-pair
    const ulonglong2* szwp = (const ulonglong2*)szw;  // .x=z-pair, .y=w-pair

    for (int c0 = 0; c0 < 4096; c0 += 2048) {
        __syncthreads();
        for (int g = t; g < 1024; g += 256) {         // pair-group g -> cand 2g,2g+1
            const float* pp = p2b + (size_t)(c0 + 2 * g) * 3;
            float x0 = pp[0], y0 = pp[1], z0 = pp[2];
            float x1 = pp[3], y1 = pp[4], z1 = pp[5];
            sxy[g] = make_float4(x0, x1, y0, y1);
            szw[g] = make_float4(z0, z1,
                                 fmaf(x0, x0, fmaf(y0, y0, z0 * z0)),
                                 fmaf(x1, x1, fmaf(y1, y1, z1 * z1)));
        }
        __syncthreads();
#pragma unroll 2
        for (int g = 0; g < 1024; g += 4) {           // 4 pair-groups = 8 cand
            ulonglong2 xy0 = sxyp[g + 0], zw0 = szwp[g + 0];
            ulonglong2 xy1 = sxyp[g + 1], zw1 = szwp[g + 1];
            ulonglong2 xy2 = sxyp[g + 2], zw2 = szwp[g + 2];
            ulonglong2 xy3 = sxyp[g + 3], zw3 = szwp[g + 3];
            unsigned long long E0 = fma2(ax2, xy0.x, fma2(ay2, xy0.y, fma2(az2, zw0.x, zw0.y)));
            unsigned long long E1 = fma2(ax2, xy1.x, fma2(ay2, xy1.y, fma2(az2, zw1.x, zw1.y)));
            unsigned long long E2 = fma2(ax2, xy2.x, fma2(ay2, xy2.y, fma2(az2, zw2.x, zw2.y)));
            unsigned long long E3 = fma2(ax2, xy3.x, fma2(ay2, xy3.y, fma2(az2, zw3.x, zw3.y)));
            float e0, e1, e2, e3, e4, e5, e6, e7;
            upk2(E0, e0, e1);
            upk2(E1, e2, e3);
            upk2(E2, e4, e5);
            upk2(E3, e6, e7);
            float m01 = fminf(e0, e1), m23 = fminf(e2, e3);
            float m45 = fminf(e4, e5), m67 = fminf(e6, e7);
            float m = fminf(fminf(m01, m23), fminf(m45, m67));
            if (m < d2) {                 // slow path: sequential inserts
                int jj = c0 + 2 * g;
                KNN_INSERT(e0, jj + 0);
                KNN_INSERT(e1, jj + 1);
                KNN_INSERT(e2, jj + 2);
                KNN_INSERT(e3, jj + 3);
                KNN_INSERT(e4, jj + 4);
                KNN_INSERT(e5, jj + 5);
                KNN_INSERT(e6, jj + 6);
                KNN_INSERT(e7, jj + 7);
            }
        }
    }
#undef KNN_INSERT

    // actual squared distances and normalized inverse-distance weights
    float D0 = d0 + s1, D1 = d1 + s1, D2 = d2 + s1;
    float r0 = 1.f / (D0 + NN_EPS);
    float r1 = 1.f / (D1 + NN_EPS);
    float r2 = 1.f / (D2 + NN_EPS);
    float inv = 1.f / (r0 + r1 + r2);
    float w0 = r0 * inv, w1 = r1 * inv, w2 = r2 * inv;

    const float4* fA = (const float4*)(g_ft + ((size_t)b * 4096 + i0) * 128);
    const float4* fB = (const float4*)(g_ft + ((size_t)b * 4096 + i1) * 128);
    const float4* fC = (const float4*)(g_ft + ((size_t)b * 4096 + i2) * 128);
    float* ob = out + (size_t)b * 128 * 16384 + q;

#pragma unroll
    for (int cc = 0; cc < 4; cc++) {
        float a[32];
#pragma unroll
        for (int u = 0; u < 8; u++) {
            float4 vA = fA[cc * 8 + u];
            float4 vB = fB[cc * 8 + u];
            float4 vC = fC[cc * 8 + u];
            a[4 * u + 0] = fmaf(w0, vA.x, fmaf(w1, vB.x, w2 * vC.x));
            a[4 * u + 1] = fmaf(w0, vA.y, fmaf(w1, vB.y, w2 * vC.y));
            a[4 * u + 2] = fmaf(w0, vA.z, fmaf(w1, vB.z, w2 * vC.z));
            a[4 * u + 3] = fmaf(w0, vA.w, fmaf(w1, vB.w, w2 * vC.w));
        }
#pragma unroll
        for (int u = 0; u < 32; u++)
            ob[(size_t)(cc * 32 + u) * 16384] = a[u];
    }
}

// ---------------------------------------------------------------------------
extern "C" void kernel_launch(void* const* d_in, const int* in_sizes, int n_in,
                              void* d_out, int out_size) {
    const float* p1  = (const float*)d_in[0];
    const float* p2  = (const float*)d_in[1];
    const float* f2  = (const float*)d_in[2];
    const float* W0  = (const float*)d_in[3];
    const float* b0  = (const float*)d_in[4];
    const float* g0  = (const float*)d_in[5];
    const float* be0 = (const float*)d_in[6];
    const float* m0  = (const float*)d_in[7];
    const float* v0  = (const float*)d_in[8];
    const float* W1  = (const float*)d_in[9];
    const float* b1  = (const float*)d_in[10];
    const float* g1  = (const float*)d_in[11];
    const float* be1 = (const float*)d_in[12];
    const float* m1  = (const float*)d_in[13];
    const float* v1  = (const float*)d_in[14];
    float* out = (float*)d_out;

    dim3 gA(4096 / 64, 8);
    fused_mlp_kernel<<<gA, 256>>>(f2, W0, b0, g0, be0, m0, v0,
                                  W1, b1, g1, be1, m1, v1);

    dim3 gB(16384 / 256, 8);             // (64, 8) = 512 blocks
    interp_kernel<<<gB, 256>>>(p1, p2, out);
}